// round 4
// baseline (speedup 1.0000x reference)
#include <cuda_runtime.h>
#include <math.h>

// Problem constants
#define BB 2
#define NQ 300
#define CC 256
#define HH 8
#define DD 32
#define LTOT 5376
#define L1SZ 4096   // 64x64
#define L2OFF 4096
#define L2SZ 1024   // 32x32
#define L3OFF 5120
#define L3SZ 256    // 16x16
#define NL (NQ*LTOT)            // 1,612,800
#define NTILES_L 42             // 5376 / 128
#define NROWS (BB*HH*NQ)        // 4800
#define SCALE 0.17677669529663687f  // 1/sqrt(32)

// ---------------- scratch (device globals; allocation-free) ----------------
__device__ float g_q[BB*NQ*CC];
__device__ float g_k[BB*LTOT*CC];
__device__ float g_v[BB*LTOT*CC];
__device__ float g_attn[(size_t)BB*HH*NQ*LTOT];   // raw scaled logits (never overwritten)
__device__ float g_f2[BB*NQ*L2SZ*HH];
__device__ float g_f3[BB*NQ*L3SZ*HH];
__device__ float g_x[BB*NQ*CC];
__device__ float g_pm[NROWS*NTILES_L];   // per-tile row max
__device__ float g_ps[NROWS*NTILES_L];   // per-tile row sumexp
__device__ float g_rowm[NROWS];          // global row max
__device__ float g_rowinv[NROWS];        // 1/sumexp

// ---------------- small projection GEMM (M=600): C = A @ W (+bias) ----------
// BM=64, BN=64, BK=16, 128 threads, per-thread 8x4
__global__ void proj_gemm_kernel(const float* __restrict__ A, const float* __restrict__ W,
                                 const float* __restrict__ bias, float* __restrict__ Cout,
                                 int M)
{
    __shared__ float As[16][68];
    __shared__ float Bs[16][68];
    int tid = threadIdx.x;
    int bm = blockIdx.y * 64;
    int bn = blockIdx.x * 64;
    int tm = (tid >> 4) * 8;
    int tn = (tid & 15) * 4;
    float acc[8][4];
    #pragma unroll
    for (int i = 0; i < 8; i++)
        #pragma unroll
        for (int j = 0; j < 4; j++) acc[i][j] = 0.f;

    for (int k0 = 0; k0 < 256; k0 += 16) {
        for (int i = tid; i < 64*16; i += 128) {
            int m = i >> 4, kk = i & 15;
            int row = bm + m;
            As[kk][m] = (row < M) ? A[(size_t)row*256 + k0 + kk] : 0.f;
        }
        for (int i = tid; i < 16*64; i += 128) {
            int kk = i >> 6, n = i & 63;
            Bs[kk][n] = W[(k0 + kk)*256 + bn + n];
        }
        __syncthreads();
        #pragma unroll
        for (int kk = 0; kk < 16; kk++) {
            float a[8], bb[4];
            *(float4*)&a[0] = *(const float4*)&As[kk][tm];
            *(float4*)&a[4] = *(const float4*)&As[kk][tm+4];
            *(float4*)&bb[0] = *(const float4*)&Bs[kk][tn];
            #pragma unroll
            for (int i = 0; i < 8; i++)
                #pragma unroll
                for (int j = 0; j < 4; j++)
                    acc[i][j] = fmaf(a[i], bb[j], acc[i][j]);
        }
        __syncthreads();
    }
    #pragma unroll
    for (int i = 0; i < 8; i++) {
        int row = bm + tm + i;
        if (row >= M) continue;
        #pragma unroll
        for (int j = 0; j < 4; j++) {
            float v = acc[i][j];
            if (bias) v += bias[bn + tn + j];
            Cout[(size_t)row*256 + bn + tn + j] = v;
        }
    }
}

// ---------------- big projection GEMM (M multiple of 128): C = A @ W ----------
// BM=128, BN=128, BK=16, 256 threads, per-thread 8x8
__global__ void __launch_bounds__(256)
proj_gemm128_kernel(const float* __restrict__ A, const float* __restrict__ W,
                    float* __restrict__ Cout)
{
    __shared__ float As[16][132];   // [k][m]
    __shared__ float Bs[16][132];   // [k][n]
    int tid = threadIdx.x;
    int bm = blockIdx.y * 128;
    int bn = blockIdx.x * 128;
    int tm = (tid >> 4) * 8;    // 16 row-groups of 8 = 128
    int tn = (tid & 15) * 8;    // 16 col-groups of 8 = 128

    float acc[8][8];
    #pragma unroll
    for (int i = 0; i < 8; i++)
        #pragma unroll
        for (int j = 0; j < 8; j++) acc[i][j] = 0.f;

    for (int k0 = 0; k0 < 256; k0 += 16) {
        // A tile: 128 rows x 16 k, float4 loads, transposed store
        #pragma unroll
        for (int i = tid; i < 128*4; i += 256) {
            int row = i >> 2, seg = i & 3;
            float4 a4 = *(const float4*)&A[(size_t)(bm + row)*256 + k0 + seg*4];
            As[seg*4+0][row] = a4.x;
            As[seg*4+1][row] = a4.y;
            As[seg*4+2][row] = a4.z;
            As[seg*4+3][row] = a4.w;
        }
        // W tile: 16 k x 128 n, float4 loads direct
        #pragma unroll
        for (int i = tid; i < 16*32; i += 256) {
            int kk = i >> 5, n4 = (i & 31) * 4;
            *(float4*)&Bs[kk][n4] = *(const float4*)&W[(k0 + kk)*256 + bn + n4];
        }
        __syncthreads();
        #pragma unroll
        for (int kk = 0; kk < 16; kk++) {
            float a[8], bb[8];
            *(float4*)&a[0]  = *(const float4*)&As[kk][tm];
            *(float4*)&a[4]  = *(const float4*)&As[kk][tm+4];
            *(float4*)&bb[0] = *(const float4*)&Bs[kk][tn];
            *(float4*)&bb[4] = *(const float4*)&Bs[kk][tn+4];
            #pragma unroll
            for (int i = 0; i < 8; i++)
                #pragma unroll
                for (int j = 0; j < 8; j++)
                    acc[i][j] = fmaf(a[i], bb[j], acc[i][j]);
        }
        __syncthreads();
    }
    #pragma unroll
    for (int i = 0; i < 8; i++) {
        #pragma unroll
        for (int j = 0; j < 8; j += 4) {
            float4 o;
            o.x = acc[i][j]; o.y = acc[i][j+1]; o.z = acc[i][j+2]; o.w = acc[i][j+3];
            *(float4*)&Cout[(size_t)(bm + tm + i)*256 + bn + tn + j] = o;
        }
    }
}

// ---------------- attention logits + per-tile softmax partials --------------
// per (b,h): BM=64 (n), BN=128 (l), K=32, 256 threads, per-thread 8x4
__global__ void attn_gemm_kernel(const float* __restrict__ Q, const float* __restrict__ K,
                                 float* __restrict__ attn,
                                 float* __restrict__ pm, float* __restrict__ ps)
{
    __shared__ float QsT[32][68];    // [k][m]
    __shared__ float KsT[32][132];   // [k][l]
    int tid = threadIdx.x;
    int bh = blockIdx.z;            // 0..15
    int b = bh >> 3, h = bh & 7;
    int nbase = blockIdx.y * 64;
    int lbase = blockIdx.x * 128;
    int tm = (tid >> 5) * 8;        // warp = tid>>5 owns rows tm..tm+7
    int tn = (tid & 31) * 4;        // lane = col group
    int lane = tid & 31;

    for (int i = tid; i < 64*32; i += 256) {
        int m = i >> 5, kk = i & 31;
        int row = nbase + m;
        QsT[kk][m] = (row < NQ) ? Q[((size_t)b*NQ + row)*CC + h*32 + kk] : 0.f;
    }
    for (int i = tid; i < 128*32; i += 256) {
        int l = i >> 5, kk = i & 31;
        KsT[kk][l] = K[((size_t)b*LTOT + lbase + l)*CC + h*32 + kk];
    }
    __syncthreads();

    float acc[8][4];
    #pragma unroll
    for (int i = 0; i < 8; i++)
        #pragma unroll
        for (int j = 0; j < 4; j++) acc[i][j] = 0.f;

    #pragma unroll
    for (int kk = 0; kk < 32; kk++) {
        float a[8], bb[4];
        *(float4*)&a[0] = *(const float4*)&QsT[kk][tm];
        *(float4*)&a[4] = *(const float4*)&QsT[kk][tm+4];
        *(float4*)&bb[0] = *(const float4*)&KsT[kk][tn];
        #pragma unroll
        for (int i = 0; i < 8; i++)
            #pragma unroll
            for (int j = 0; j < 4; j++)
                acc[i][j] = fmaf(a[i], bb[j], acc[i][j]);
    }

    #pragma unroll
    for (int i = 0; i < 8; i++) {
        int row = nbase + tm + i;
        float o0 = acc[i][0] * SCALE;
        float o1 = acc[i][1] * SCALE;
        float o2 = acc[i][2] * SCALE;
        float o3 = acc[i][3] * SCALE;
        if (row < NQ) {
            float4 o; o.x = o0; o.y = o1; o.z = o2; o.w = o3;
            *(float4*)&attn[((size_t)bh*NQ + row)*LTOT + lbase + tn] = o;
        }
        // per-row softmax partials over this 128-col tile (warp-wide reduce)
        float m = fmaxf(fmaxf(o0, o1), fmaxf(o2, o3));
        #pragma unroll
        for (int s = 16; s > 0; s >>= 1)
            m = fmaxf(m, __shfl_xor_sync(0xffffffffu, m, s));
        float sum = __expf(o0 - m) + __expf(o1 - m) + __expf(o2 - m) + __expf(o3 - m);
        #pragma unroll
        for (int s = 16; s > 0; s >>= 1)
            sum += __shfl_xor_sync(0xffffffffu, sum, s);
        if (lane == 0 && row < NQ) {
            size_t pidx = ((size_t)bh*NQ + row)*NTILES_L + blockIdx.x;
            pm[pidx] = m;
            ps[pidx] = sum;
        }
    }
}

// ---------------- combine per-tile partials into per-row (max, 1/sum) -------
// one warp per row; 8 rows per block
__global__ void softstats_kernel(const float* __restrict__ pm, const float* __restrict__ ps,
                                 float* __restrict__ rowm, float* __restrict__ rowinv)
{
    int row = blockIdx.x * 8 + (threadIdx.x >> 5);
    int lane = threadIdx.x & 31;
    size_t base = (size_t)row * NTILES_L;
    float m1 = (lane < NTILES_L) ? pm[base + lane] : -1e30f;
    float m2 = (lane + 32 < NTILES_L) ? pm[base + lane + 32] : -1e30f;
    float m = fmaxf(m1, m2);
    #pragma unroll
    for (int s = 16; s > 0; s >>= 1)
        m = fmaxf(m, __shfl_xor_sync(0xffffffffu, m, s));
    float s1 = (lane < NTILES_L) ? ps[base + lane] * __expf(m1 - m) : 0.f;
    float s2 = (lane + 32 < NTILES_L) ? ps[base + lane + 32] * __expf(m2 - m) : 0.f;
    float ssum = s1 + s2;
    #pragma unroll
    for (int s = 16; s > 0; s >>= 1)
        ssum += __shfl_xor_sync(0xffffffffu, ssum, s);
    if (lane == 0) {
        rowm[row] = m;
        rowinv[row] = 1.f / ssum;
    }
}

// ---------------- f2/f3 small fields: relu(ap @ W + b), channel-last --------
__global__ void f23_kernel(const float* __restrict__ attn,
                           const float* __restrict__ W2, const float* __restrict__ b2,
                           const float* __restrict__ W3, const float* __restrict__ b3,
                           float* __restrict__ f2o, float* __restrict__ f3o)
{
    int bn = blockIdx.y;
    int b = bn / NQ, n = bn % NQ;
    int j = blockIdx.x * blockDim.x + threadIdx.x;
    if (j >= L2SZ + L3SZ) return;

    int lidx = (j < L2SZ) ? (L2OFF + j) : (L3OFF + (j - L2SZ));
    size_t base = ((size_t)(b*HH)*NQ + n)*LTOT + lidx;
    float a[8];
    #pragma unroll
    for (int hh = 0; hh < 8; hh++)
        a[hh] = attn[base + (size_t)hh * NL];

    if (j < L2SZ) {
        float* dst = f2o + ((size_t)bn * L2SZ + j) * 8;
        #pragma unroll
        for (int h = 0; h < 8; h++) {
            float s = b2[h];
            #pragma unroll
            for (int hh = 0; hh < 8; hh++) s = fmaf(a[hh], W2[hh*8 + h], s);
            dst[h] = fmaxf(s, 0.f);
        }
    } else {
        int jj = j - L2SZ;
        float* dst = f3o + ((size_t)bn * L3SZ + jj) * 8;
        #pragma unroll
        for (int h = 0; h < 8; h++) {
            float s = b3[h];
            #pragma unroll
            for (int hh = 0; hh < 8; hh++) s = fmaf(a[hh], W3[hh*8 + h], s);
            dst[h] = fmaxf(s, 0.f);
        }
    }
}

// ---------------- fused mask: f1 + bilinear(f2) + bilinear(f3), dot Wm, relu -
__global__ void mask_kernel(const float* __restrict__ attn,
                            const float* __restrict__ f2f, const float* __restrict__ f3f,
                            const float* __restrict__ W1, const float* __restrict__ b1,
                            const float* __restrict__ Wm, const float* __restrict__ bm,
                            float* __restrict__ outmask)
{
    __shared__ float sW1[64], sb1[8], sWm[24], sbm[1];
    int t = threadIdx.x;
    if (t < 64) sW1[t] = W1[t];
    if (t < 8)  sb1[t] = b1[t];
    if (t < 24) sWm[t] = Wm[t];
    if (t == 0) sbm[0] = bm[0];
    __syncthreads();

    int bn = blockIdx.y;
    int b = bn / NQ, n = bn % NQ;
    int p = blockIdx.x * blockDim.x + t;
    int Y = p >> 6, X = p & 63;

    size_t base = ((size_t)(b*HH)*NQ + n)*LTOT + p;
    float a[8];
    #pragma unroll
    for (int hh = 0; hh < 8; hh++)
        a[hh] = attn[base + (size_t)hh * NL];

    float acc = sbm[0];
    #pragma unroll
    for (int h = 0; h < 8; h++) {
        float s = sb1[h];
        #pragma unroll
        for (int hh = 0; hh < 8; hh++) s = fmaf(a[hh], sW1[hh*8 + h], s);
        acc = fmaf(fmaxf(s, 0.f), sWm[h], acc);
    }

    {   // f2: bilinear from 32x32
        float ry = fminf(fmaxf(0.5f*(float)Y - 0.25f, 0.f), 31.f);
        float rx = fminf(fmaxf(0.5f*(float)X - 0.25f, 0.f), 31.f);
        int y0 = (int)ry, x0 = (int)rx;
        int y1 = min(y0+1, 31), x1 = min(x0+1, 31);
        float wy = ry - (float)y0, wx = rx - (float)x0;
        float w00 = (1.f-wy)*(1.f-wx), w01 = (1.f-wy)*wx, w10 = wy*(1.f-wx), w11 = wy*wx;
        const float* fb = f2f + (size_t)bn * (L2SZ*8);
        const float* t00 = fb + (y0*32 + x0)*8;
        const float* t01 = fb + (y0*32 + x1)*8;
        const float* t10 = fb + (y1*32 + x0)*8;
        const float* t11 = fb + (y1*32 + x1)*8;
        #pragma unroll
        for (int h = 0; h < 8; h++) {
            float v = w00*t00[h] + w01*t01[h] + w10*t10[h] + w11*t11[h];
            acc = fmaf(v, sWm[8 + h], acc);
        }
    }
    {   // f3: bilinear from 16x16
        float ry = fminf(fmaxf(0.25f*(float)Y - 0.375f, 0.f), 15.f);
        float rx = fminf(fmaxf(0.25f*(float)X - 0.375f, 0.f), 15.f);
        int y0 = (int)ry, x0 = (int)rx;
        int y1 = min(y0+1, 15), x1 = min(x0+1, 15);
        float wy = ry - (float)y0, wx = rx - (float)x0;
        float w00 = (1.f-wy)*(1.f-wx), w01 = (1.f-wy)*wx, w10 = wy*(1.f-wx), w11 = wy*wx;
        const float* fb = f3f + (size_t)bn * (L3SZ*8);
        const float* t00 = fb + (y0*16 + x0)*8;
        const float* t01 = fb + (y0*16 + x1)*8;
        const float* t10 = fb + (y1*16 + x0)*8;
        const float* t11 = fb + (y1*16 + x1)*8;
        #pragma unroll
        for (int h = 0; h < 8; h++) {
            float v = w00*t00[h] + w01*t01[h] + w10*t10[h] + w11*t11[h];
            acc = fmaf(v, sWm[16 + h], acc);
        }
    }
    outmask[(size_t)bn * L1SZ + p] = fmaxf(acc, 0.f);
}

// ---------------- zero ----
__global__ void zero_kernel(float* __restrict__ p, int n)
{
    int i = blockIdx.x * blockDim.x + threadIdx.x;
    if (i < n) p[i] = 0.f;
}

// ---------------- AV: probs computed on the fly from raw logits -------------
// per (b,h): BM=64 (n), BN=32 (d), BK=32, 128 threads, L split x4 with atomics
__global__ void av_kernel(const float* __restrict__ attn, const float* __restrict__ V,
                          const float* __restrict__ rowm, const float* __restrict__ rowinv,
                          float* __restrict__ X)
{
    __shared__ float As[32][68];   // [k][m] holds probabilities
    __shared__ float Bs[32][32];   // [k][d]
    __shared__ float srm[64], sri[64];
    int tid = threadIdx.x;
    int bh = blockIdx.z;
    int b = bh >> 3, h = bh & 7;
    int nbase = blockIdx.y * 64;
    int l0 = blockIdx.x * 1344;
    int tm = (tid >> 4) * 8;
    int tn = (tid & 15) * 2;

    if (tid < 64) {
        int row = nbase + tid;
        bool ok = row < NQ;
        srm[tid] = ok ? rowm[(size_t)bh*NQ + row] : 0.f;
        sri[tid] = ok ? rowinv[(size_t)bh*NQ + row] : 0.f;
    }
    __syncthreads();

    float acc[8][2];
    #pragma unroll
    for (int i = 0; i < 8; i++) { acc[i][0] = 0.f; acc[i][1] = 0.f; }

    for (int k0 = l0; k0 < l0 + 1344; k0 += 32) {
        for (int i = tid; i < 64*32; i += 128) {
            int m = i >> 5, kk = i & 31;
            int row = nbase + m;
            float p = 0.f;
            if (row < NQ) {
                float v = attn[((size_t)bh*NQ + row)*LTOT + k0 + kk];
                p = __expf(v - srm[m]) * sri[m];
            }
            As[kk][m] = p;
        }
        for (int i = tid; i < 32*32; i += 128) {
            int kk = i >> 5, d = i & 31;
            Bs[kk][d] = V[((size_t)b*LTOT + k0 + kk)*CC + h*32 + d];
        }
        __syncthreads();
        #pragma unroll
        for (int kk = 0; kk < 32; kk++) {
            float a[8];
            *(float4*)&a[0] = *(const float4*)&As[kk][tm];
            *(float4*)&a[4] = *(const float4*)&As[kk][tm+4];
            float b0 = Bs[kk][tn], b1 = Bs[kk][tn+1];
            #pragma unroll
            for (int i = 0; i < 8; i++) {
                acc[i][0] = fmaf(a[i], b0, acc[i][0]);
                acc[i][1] = fmaf(a[i], b1, acc[i][1]);
            }
        }
        __syncthreads();
    }
    #pragma unroll
    for (int i = 0; i < 8; i++) {
        int row = nbase + tm + i;
        if (row >= NQ) continue;
        atomicAdd(&X[((size_t)b*NQ + row)*CC + h*32 + tn    ], acc[i][0]);
        atomicAdd(&X[((size_t)b*NQ + row)*CC + h*32 + tn + 1], acc[i][1]);
    }
}

// ---------------- launch ----
extern "C" void kernel_launch(void* const* d_in, const int* in_sizes, int n_in,
                              void* d_out, int out_size)
{
    const float* query = (const float*)d_in[0];
    const float* key   = (const float*)d_in[1];
    const float* value = (const float*)d_in[2];
    const float* Wq = (const float*)d_in[5];
    const float* Wk = (const float*)d_in[6];
    const float* Wv = (const float*)d_in[7];
    const float* Wp = (const float*)d_in[8];
    const float* bp = (const float*)d_in[9];
    const float* W1 = (const float*)d_in[10];
    const float* b1 = (const float*)d_in[11];
    const float* W2 = (const float*)d_in[12];
    const float* b2 = (const float*)d_in[13];
    const float* W3 = (const float*)d_in[14];
    const float* b3 = (const float*)d_in[15];
    const float* Wm = (const float*)d_in[16];
    const float* bm = (const float*)d_in[17];

    float* out_x    = (float*)d_out;
    float* out_mask = (float*)d_out + BB*NQ*CC;

    float *gq, *gk, *gv, *gattn, *gf2, *gf3, *gx, *gpm, *gps, *grm, *gri;
    cudaGetSymbolAddress((void**)&gq,    g_q);
    cudaGetSymbolAddress((void**)&gk,    g_k);
    cudaGetSymbolAddress((void**)&gv,    g_v);
    cudaGetSymbolAddress((void**)&gattn, g_attn);
    cudaGetSymbolAddress((void**)&gf2,   g_f2);
    cudaGetSymbolAddress((void**)&gf3,   g_f3);
    cudaGetSymbolAddress((void**)&gx,    g_x);
    cudaGetSymbolAddress((void**)&gpm,   g_pm);
    cudaGetSymbolAddress((void**)&gps,   g_ps);
    cudaGetSymbolAddress((void**)&grm,   g_rowm);
    cudaGetSymbolAddress((void**)&gri,   g_rowinv);

    // 1) projections (K/V are 10752 rows = 84 x 128: big-tile kernel)
    proj_gemm_kernel<<<dim3(4, 10), 128>>>(query, Wq, nullptr, gq, BB*NQ);
    proj_gemm128_kernel<<<dim3(2, 84), 256>>>(key,   Wk, gk);
    proj_gemm128_kernel<<<dim3(2, 84), 256>>>(value, Wv, gv);

    // 2) attention logits + per-tile softmax partials
    attn_gemm_kernel<<<dim3(NTILES_L, 5, 16), 256>>>(gq, gk, gattn, gpm, gps);

    // 3) per-row softmax stats (replaces the full softmax pass)
    softstats_kernel<<<NROWS/8, 256>>>(gpm, gps, grm, gri);

    // 4) mask path (reads raw logits)
    f23_kernel<<<dim3(5, 600), 256>>>(gattn, W2, b2, W3, b3, gf2, gf3);
    mask_kernel<<<dim3(32, 600), 128>>>(gattn, gf2, gf3, W1, b1, Wm, bm, out_mask);

    // 5) AV with on-the-fly normalization
    zero_kernel<<<(BB*NQ*CC + 255)/256, 256>>>(gx, BB*NQ*CC);
    av_kernel<<<dim3(4, 5, 16), 128>>>(gattn, gv, grm, gri, gx);

    // 6) output projection
    proj_gemm_kernel<<<dim3(4, 10), 128>>>(gx, Wp, bp, out_x, BB*NQ);
}